// round 4
// baseline (speedup 1.0000x reference)
#include <cuda_runtime.h>

// weight: [2304, 1280] fp32 (G=48); grid_thw = [[2,64,64]]*8
// output: 65536 x 1280 fp32 (335.5 MB) — pure DRAM-write-bound.
//
// Output row = k*4096 + hb*128 + wb*4 + (hm*2+wm), k = 2e+t in [0,16).
// Compute each distinct (h,w) row once, store 16 k-replicas with streaming
// hint (__stcs / .cs keeps the 11.8MB weight table L2-resident across graph
// replays — confirmed win in R2; R3's occupancy boost was a confirmed loss).
//
// R4: one CTA per (hb,wb) patch, 640 threads = 4 sub-rows x 160 v8-columns.
// Stores use 256-bit st.global.cs.v8.f32 (sm_100+): half the store
// instructions / L2 write requests -> larger write transactions to DRAM.

#define G_    48
#define D_    1280
#define V8_   160                 // 8-float columns per row
#define REPS  16
#define ROWSTRIDE_F (4096 * D_)   // float stride between k-replicas

__global__ __launch_bounds__(640)
void pe_patch_v8_kernel(const float* __restrict__ W, float* __restrict__ out)
{
    const int pid = blockIdx.x;          // 0..1023
    const int hb  = pid >> 5;            // 0..31
    const int wb  = pid & 31;            // 0..31

    const int tid = threadIdx.x;         // 0..639
    const int m   = tid / V8_;           // sub-row 0..3  (m = hm*2 + wm)
    const int c8  = tid - m * V8_;       // v8 column 0..159

    const int hm = m >> 1;
    const int wm = m & 1;
    const int h  = 2 * hb + hm;
    const int w  = 2 * wb + wm;

    // linspace(0,47,64): v = i*47/63; integer numerator first -> exact floor
    const float vh = (float)(h * (G_ - 1)) * (1.0f / 63.0f);
    const float vw = (float)(w * (G_ - 1)) * (1.0f / 63.0f);
    const int hf = (int)vh;
    const int wf = (int)vw;
    const int hc = min(hf + 1, G_ - 1);
    const int wc = min(wf + 1, G_ - 1);
    const float dh = vh - (float)hf;
    const float dw = vw - (float)wf;

    const float c00 = (1.0f - dh) * (1.0f - dw);
    const float c01 = (1.0f - dh) * dw;
    const float c10 = dh * (1.0f - dw);
    const float c11 = dh * dw;

    const float* r00 = W + (size_t)(hf * G_ + wf) * D_ + 8 * c8;
    const float* r01 = W + (size_t)(hf * G_ + wc) * D_ + 8 * c8;
    const float* r10 = W + (size_t)(hc * G_ + wf) * D_ + 8 * c8;
    const float* r11 = W + (size_t)(hc * G_ + wc) * D_ + 8 * c8;

    // 8 floats per thread (two float4 halves per corner)
    float4 a0 = ((const float4*)r00)[0], a1 = ((const float4*)r00)[1];
    float4 b0 = ((const float4*)r01)[0], b1 = ((const float4*)r01)[1];
    float4 p0 = ((const float4*)r10)[0], p1 = ((const float4*)r10)[1];
    float4 q0 = ((const float4*)r11)[0], q1 = ((const float4*)r11)[1];

    float v[8];
    v[0] = c00*a0.x + c01*b0.x + c10*p0.x + c11*q0.x;
    v[1] = c00*a0.y + c01*b0.y + c10*p0.y + c11*q0.y;
    v[2] = c00*a0.z + c01*b0.z + c10*p0.z + c11*q0.z;
    v[3] = c00*a0.w + c01*b0.w + c10*p0.w + c11*q0.w;
    v[4] = c00*a1.x + c01*b1.x + c10*p1.x + c11*q1.x;
    v[5] = c00*a1.y + c01*b1.y + c10*p1.y + c11*q1.y;
    v[6] = c00*a1.z + c01*b1.z + c10*p1.z + c11*q1.z;
    v[7] = c00*a1.w + c01*b1.w + c10*p1.w + c11*q1.w;

    // base output row of this patch + sub-row
    const int rloc = hb * 128 + wb * 4 + m;
    float* o = out + (size_t)rloc * D_ + 8 * c8;

    #pragma unroll
    for (int k = 0; k < REPS; ++k) {
        float* dst = o + (size_t)k * ROWSTRIDE_F;
        asm volatile(
            "st.global.cs.v8.f32 [%0], {%1,%2,%3,%4,%5,%6,%7,%8};"
            :: "l"(dst),
               "f"(v[0]), "f"(v[1]), "f"(v[2]), "f"(v[3]),
               "f"(v[4]), "f"(v[5]), "f"(v[6]), "f"(v[7])
            : "memory");
    }
}

extern "C" void kernel_launch(void* const* d_in, const int* in_sizes, int n_in,
                              void* d_out, int out_size)
{
    const float* weight = (const float*)d_in[0];
    (void)in_sizes; (void)n_in; (void)out_size;
    pe_patch_v8_kernel<<<1024, 640>>>(weight, (float*)d_out);
}